// round 5
// baseline (speedup 1.0000x reference)
#include <cuda_runtime.h>

// out[b,h,w,c] = sum_j w[j,c] * t_j[b,h,w,c]
// t_j = (8,128,128,128) fp32 contiguous; w = (5,128) fp32.
// N = 16,777,216 floats -> 4,194,304 float4. HBM-bound: 384 MiB total traffic.
//
// Each thread handles 2 float4s at block-stride 256. Since 256 % 32 == 0 the
// channel phase (idx & 31) is identical for both, so one set of weight loads
// serves both elements. 10 independent LDG.128 front-batched per thread.

__global__ __launch_bounds__(256, 8)
void merge5_kernel(const float4* __restrict__ t1,
                   const float4* __restrict__ t2,
                   const float4* __restrict__ t3,
                   const float4* __restrict__ t4,
                   const float4* __restrict__ t5,
                   const float4* __restrict__ w,   // (5,32) float4 = (5,128) floats
                   float4* __restrict__ out,
                   int n4) {
    int idx0 = blockIdx.x * (blockDim.x * 2) + threadIdx.x;  // first element
    int idx1 = idx0 + 256;                                    // second element
    if (idx0 >= n4) return;

    int cw = idx0 & 31;  // channel-phase float4 index (same for idx1)

    // Weights: 2.5 KB, L1-resident after first wave.
    float4 w0 = __ldg(&w[0 * 32 + cw]);
    float4 w1 = __ldg(&w[1 * 32 + cw]);
    float4 w2 = __ldg(&w[2 * 32 + cw]);
    float4 w3 = __ldg(&w[3 * 32 + cw]);
    float4 w4 = __ldg(&w[4 * 32 + cw]);

    // Front-batch 10 independent streaming loads (evict-first: read-once data).
    float4 a0 = __ldcs(&t1[idx0]);
    float4 b0 = __ldcs(&t2[idx0]);
    float4 c0 = __ldcs(&t3[idx0]);
    float4 d0 = __ldcs(&t4[idx0]);
    float4 e0 = __ldcs(&t5[idx0]);

    bool has1 = (idx1 < n4);
    float4 a1, b1, c1, d1, e1;
    if (has1) {
        a1 = __ldcs(&t1[idx1]);
        b1 = __ldcs(&t2[idx1]);
        c1 = __ldcs(&t3[idx1]);
        d1 = __ldcs(&t4[idx1]);
        e1 = __ldcs(&t5[idx1]);
    }

    float4 o0;
    o0.x = a0.x * w0.x + b0.x * w1.x + c0.x * w2.x + d0.x * w3.x + e0.x * w4.x;
    o0.y = a0.y * w0.y + b0.y * w1.y + c0.y * w2.y + d0.y * w3.y + e0.y * w4.y;
    o0.z = a0.z * w0.z + b0.z * w1.z + c0.z * w2.z + d0.z * w3.z + e0.z * w4.z;
    o0.w = a0.w * w0.w + b0.w * w1.w + c0.w * w2.w + d0.w * w3.w + e0.w * w4.w;
    __stcs(&out[idx0], o0);

    if (has1) {
        float4 o1;
        o1.x = a1.x * w0.x + b1.x * w1.x + c1.x * w2.x + d1.x * w3.x + e1.x * w4.x;
        o1.y = a1.y * w0.y + b1.y * w1.y + c1.y * w2.y + d1.y * w3.y + e1.y * w4.y;
        o1.z = a1.z * w0.z + b1.z * w1.z + c1.z * w2.z + d1.z * w3.z + e1.z * w4.z;
        o1.w = a1.w * w0.w + b1.w * w1.w + c1.w * w2.w + d1.w * w3.w + e1.w * w4.w;
        __stcs(&out[idx1], o1);
    }
}

extern "C" void kernel_launch(void* const* d_in, const int* in_sizes, int n_in,
                              void* d_out, int out_size) {
    const float4* t1 = (const float4*)d_in[0];
    const float4* t2 = (const float4*)d_in[1];
    const float4* t3 = (const float4*)d_in[2];
    const float4* t4 = (const float4*)d_in[3];
    const float4* t5 = (const float4*)d_in[4];
    const float4* w  = (const float4*)d_in[5];
    float4* out = (float4*)d_out;

    int n4 = out_size / 4;                 // 4,194,304
    int threads = 256;
    int per_block = threads * 2;           // 512 float4 per block
    int blocks = (n4 + per_block - 1) / per_block;  // 8192
    merge5_kernel<<<blocks, threads>>>(t1, t2, t3, t4, t5, w, out, n4);
}

// round 7
// speedup vs baseline: 1.3517x; 1.3517x over previous
#include <cuda_runtime.h>

// out[b,h,w,c] = sum_j w[j,c] * t_j[b,h,w,c]
// t_j = (8,128,128,128) fp32 contiguous; w = (5,128) fp32.
// N = 16,777,216 floats -> 4,194,304 float4. HBM-bound: 384 MiB mandatory traffic.
//
// R3 shape (proven 85.4% DRAM): 1 float4/thread, 5 front-batched LDG.128.
// R5 deltas: launch_bounds relaxed (R4's minBlocks=8 cap at 32 regs caused
// local-memory spills in the 2x variant), streaming evict-first hints on the
// read-once tensors and write-once output.

__global__ __launch_bounds__(256, 4)
void merge5_kernel(const float4* __restrict__ t1,
                   const float4* __restrict__ t2,
                   const float4* __restrict__ t3,
                   const float4* __restrict__ t4,
                   const float4* __restrict__ t5,
                   const float4* __restrict__ w,   // (5,32) float4 = (5,128) floats
                   float4* __restrict__ out,
                   int n4) {
    int idx = blockIdx.x * blockDim.x + threadIdx.x;
    if (idx >= n4) return;

    int cw = idx & 31;  // float4 index within the 128-channel row

    // Weights: 2.5 KB, cache-resident, reused by every thread -> default policy.
    float4 w0 = __ldg(&w[0 * 32 + cw]);
    float4 w1 = __ldg(&w[1 * 32 + cw]);
    float4 w2 = __ldg(&w[2 * 32 + cw]);
    float4 w3 = __ldg(&w[3 * 32 + cw]);
    float4 w4 = __ldg(&w[4 * 32 + cw]);

    // 5 independent streaming loads, front-batched (MLP=5/thread).
    float4 a = __ldcs(&t1[idx]);
    float4 b = __ldcs(&t2[idx]);
    float4 c = __ldcs(&t3[idx]);
    float4 d = __ldcs(&t4[idx]);
    float4 e = __ldcs(&t5[idx]);

    float4 o;
    o.x = a.x * w0.x + b.x * w1.x + c.x * w2.x + d.x * w3.x + e.x * w4.x;
    o.y = a.y * w0.y + b.y * w1.y + c.y * w2.y + d.y * w3.y + e.y * w4.y;
    o.z = a.z * w0.z + b.z * w1.z + c.z * w2.z + d.z * w3.z + e.z * w4.z;
    o.w = a.w * w0.w + b.w * w1.w + c.w * w2.w + d.w * w3.w + e.w * w4.w;

    __stcs(&out[idx], o);
}

extern "C" void kernel_launch(void* const* d_in, const int* in_sizes, int n_in,
                              void* d_out, int out_size) {
    const float4* t1 = (const float4*)d_in[0];
    const float4* t2 = (const float4*)d_in[1];
    const float4* t3 = (const float4*)d_in[2];
    const float4* t4 = (const float4*)d_in[3];
    const float4* t5 = (const float4*)d_in[4];
    const float4* w  = (const float4*)d_in[5];
    float4* out = (float4*)d_out;

    int n4 = out_size / 4;  // 4,194,304
    int threads = 256;
    int blocks = (n4 + threads - 1) / threads;  // 16384 blocks
    merge5_kernel<<<blocks, threads>>>(t1, t2, t3, t4, t5, w, out, n4);
}